// round 13
// baseline (speedup 1.0000x reference)
#include <cuda_runtime.h>
#include <cstddef>

#define L_SEQ 512
#define B_SZ  64
#define D_IN  512
#define HALFH 256
#define G4    1024                 // 4*HALF gate rows per direction
#define M_TOT (L_SEQ * B_SZ)      // 32768
#define NBPD  64                  // blocks per direction in recurrence
#define HB    4                   // hidden units per block

typedef unsigned long long u64;

// ---------------------------------------------------------------------------
// Packed fp32x2 helpers (sm_100+). IEEE fp32 per lane -> bit-identical math.
// ---------------------------------------------------------------------------
__device__ __forceinline__ u64 f2_dup(float v) {
    u64 r; asm("mov.b64 %0, {%1, %1};" : "=l"(r) : "f"(v)); return r;
}
__device__ __forceinline__ void f2_unpack(u64 p, float& lo, float& hi) {
    asm("mov.b64 {%0, %1}, %2;" : "=f"(lo), "=f"(hi) : "l"(p));
}
__device__ __forceinline__ u64 f2_fma(u64 a, u64 b, u64 c) {
    u64 d; asm("fma.rn.f32x2 %0, %1, %2, %3;" : "=l"(d) : "l"(a), "l"(b), "l"(c));
    return d;
}

// Fast tanh via MUFU: tanh(x) = 1 - 2/(e^{2x}+1). Saturates correctly.
__device__ __forceinline__ float fast_tanh(float x) {
    float e = __expf(2.0f * x);
    return 1.0f - __fdividef(2.0f, e + 1.0f);
}

// Morally-strong gpu-scope acquire/release on u32 (bypass L1, no IVALL).
__device__ __forceinline__ unsigned ld_acq(const unsigned* p) {
    unsigned v;
    asm volatile("ld.acquire.gpu.global.u32 %0, [%1];" : "=r"(v) : "l"(p) : "memory");
    return v;
}
__device__ __forceinline__ void st_rel(unsigned* p, unsigned v) {
    asm volatile("st.release.gpu.global.u32 [%0], %1;" :: "l"(p), "r"(v) : "memory");
}

// Scratch: xw[dir][g][m] with m = l*B + b   (256 MB, module-static: allowed)
__device__ float g_xw[(size_t)2 * G4 * M_TOT];
// Double-buffered hidden state: [dir][buf][b][k]
__device__ float g_h[2][2][B_SZ][HALFH];
// Flag barrier: per-block flags, 32B stride (no false sharing).
__device__ unsigned g_flag[2][NBPD * 8];
// Cross-replay monotonic base (written once per launch by blk_local 0).
__device__ unsigned g_gen[2][32];

// ---------------------------------------------------------------------------
// Kernel 1: xw[dir][g][m] = sum_d W_ih[g][d] * x[m][d] + b_ih[g] + b_hh[g]
// Tiles: 64(g) x 64(m) x 16(k), 256 threads, 4x4 register tile, FFMA2 math.
// ---------------------------------------------------------------------------
__global__ __launch_bounds__(256) void gemm_xw_kernel(
    const float* __restrict__ x,
    const float* __restrict__ Wf, const float* __restrict__ Wb,
    const float* __restrict__ bihf, const float* __restrict__ bhhf,
    const float* __restrict__ bihb, const float* __restrict__ bhhb)
{
    const int dir = blockIdx.z;
    const float* __restrict__ W   = dir ? Wb   : Wf;
    const float* __restrict__ bih = dir ? bihb : bihf;
    const float* __restrict__ bhh = dir ? bhhb : bhhf;

    const int m0 = blockIdx.x * 64;
    const int g0 = blockIdx.y * 64;

    __shared__ float As[16][68];   // As[k][g']
    __shared__ float Bs[16][68];   // Bs[k][m']

    const int tid = threadIdx.x;
    const int tx  = tid & 15;      // m sub-tile
    const int ty  = tid >> 4;      // g sub-tile

    const int lrow = tid >> 2;          // 0..63 (tile row to load)
    const int lc   = (tid & 3) * 4;     // k offset 0,4,8,12

    const float* Arow = W + (size_t)(g0 + lrow) * D_IN + lc;
    const float* Brow = x + (size_t)(m0 + lrow) * D_IN + lc;

    u64 acc2[4][2] = {};

    for (int k0 = 0; k0 < D_IN; k0 += 16) {
        float4 av = *(const float4*)(Arow + k0);
        float4 bv = *(const float4*)(Brow + k0);
        __syncthreads();
        As[lc + 0][lrow] = av.x; As[lc + 1][lrow] = av.y;
        As[lc + 2][lrow] = av.z; As[lc + 3][lrow] = av.w;
        Bs[lc + 0][lrow] = bv.x; Bs[lc + 1][lrow] = bv.y;
        Bs[lc + 2][lrow] = bv.z; Bs[lc + 3][lrow] = bv.w;
        __syncthreads();
#pragma unroll
        for (int kk = 0; kk < 16; kk++) {
            float4     a  = *(const float4*)&As[kk][ty * 4];
            ulonglong2 bp = *(const ulonglong2*)&Bs[kk][tx * 4];
            u64 d0 = f2_dup(a.x), d1 = f2_dup(a.y),
                d2 = f2_dup(a.z), d3 = f2_dup(a.w);
            acc2[0][0] = f2_fma(d0, bp.x, acc2[0][0]);
            acc2[0][1] = f2_fma(d0, bp.y, acc2[0][1]);
            acc2[1][0] = f2_fma(d1, bp.x, acc2[1][0]);
            acc2[1][1] = f2_fma(d1, bp.y, acc2[1][1]);
            acc2[2][0] = f2_fma(d2, bp.x, acc2[2][0]);
            acc2[2][1] = f2_fma(d2, bp.y, acc2[2][1]);
            acc2[3][0] = f2_fma(d3, bp.x, acc2[3][0]);
            acc2[3][1] = f2_fma(d3, bp.y, acc2[3][1]);
        }
    }

#pragma unroll
    for (int i = 0; i < 4; i++) {
        int g = g0 + ty * 4 + i;
        float bb = bih[g] + bhh[g];
        float c0, c1, c2, c3;
        f2_unpack(acc2[i][0], c0, c1);
        f2_unpack(acc2[i][1], c2, c3);
        float4 o;
        o.x = c0 + bb; o.y = c1 + bb; o.z = c2 + bb; o.w = c3 + bb;
        size_t base = ((size_t)dir * G4 + g) * M_TOT + m0 + tx * 4;
        *(float4*)&g_xw[base] = o;
    }
}

// ---------------------------------------------------------------------------
// SINGLE-HOP flag barrier over the NBPD blocks of one direction.
// Arrival: one st.release.gpu to this block's 32B-padded flag.
// Wait: EVERY block's threads 0..NBPD-1 acquire-spin directly on the 64
// flags (one flag per thread), then bar.sync composes the 64 acquire-HB
// edges block-wide. No leader, no gen hop -> one L2 round trip total.
// ---------------------------------------------------------------------------
__device__ __forceinline__ void barrier_arrive(int dir, int blk_local,
                                               unsigned target, int tid)
{
    if (tid == 0)
        st_rel(&g_flag[dir][blk_local * 8], target);
}
__device__ __forceinline__ void barrier_spin(int dir, unsigned target, int tid)
{
    if (tid < NBPD) {
        unsigned v;
        do { v = ld_acq(&g_flag[dir][tid * 8]); }
        while ((int)(v - target) < 0);
    }
    __syncthreads();
}

// ---------------------------------------------------------------------------
// Kernel 2: persistent bidirectional LSTM recurrence.
// 128 blocks (<=148 SMs, co-resident), 256 threads; thread (b,q) owns cell
// (b, j0+q) and all 4 of its gates.
// K-PAIRED accumulation; coalesced h write-back; out STG after release;
// MUFU-based tanh on the serial cell-update chain.
// Dynamic SMEM: h_s[64][260] + W_s[16][260] + hout[4][64] = 84224 B
// ---------------------------------------------------------------------------
__global__ __launch_bounds__(256, 1) void lstm_rec_kernel(
    const float* __restrict__ mask,
    const float* __restrict__ Whhf, const float* __restrict__ Whhb,
    float* __restrict__ out)
{
    extern __shared__ float smem[];
    float (*h_s)[260] = (float(*)[260])smem;                      // 64 x 260
    float (*W_s)[260] = (float(*)[260])(smem + 64 * 260);         // 16 x 260
    float (*hout)[64] = (float(*)[64])(smem + 64 * 260 + 16 * 260); // 4 x 64

    const int blk = blockIdx.x;
    const int dir = blk >> 6;
    const int blk_local = blk & 63;
    const int j0  = blk_local * HB;
    const float* __restrict__ Whh = dir ? Whhb : Whhf;

    const int tid = threadIdx.x;
    const int b   = tid & 63;     // batch lane
    const int q   = tid >> 6;     // local hidden unit owned by this thread

    // Monotonic barrier base from previous launch (all threads read same).
    const unsigned base = ld_acq(&g_gen[dir][0]);

    // Load W slice row-major: W_s[jj*4+gt][k] = Whh[gt*HALF + j0 + jj][k].
    for (int idx = tid; idx < 16 * 64; idx += 256) {
        int r = idx >> 6, kq = idx & 63;
        int jj = r >> 2, gt = r & 3;
        float4 w4 = *(const float4*)&Whh[(size_t)(gt * HALFH + j0 + jj) * HALFH + kq * 4];
        *(float4*)&W_s[r][kq * 4] = w4;
    }

    // Zero our slice of the step-0 read buffer; c lives in a register.
    g_h[dir][0][b][j0 + q] = 0.0f;
    float c = 0.0f;

    __syncthreads();                              // zeros + W staged
    barrier_arrive(dir, blk_local, base + 1, tid);
    barrier_spin(dir, base + 1, tid);             // zeros visible to all

    const float* __restrict__ Wr0 = &W_s[q * 4 + 0][0];   // gate i row
    const float* __restrict__ Wr1 = &W_s[q * 4 + 1][0];   // gate f row
    const float* __restrict__ Wr2 = &W_s[q * 4 + 2][0];   // gate g row
    const float* __restrict__ Wr3 = &W_s[q * 4 + 3][0];   // gate o row

    // Strength-reduced stream pointers (stride +/-B_SZ per step).
    const int t0 = dir ? (L_SEQ - 1) : 0;
    const ptrdiff_t dstep = dir ? -(ptrdiff_t)B_SZ : (ptrdiff_t)B_SZ;
    const float* __restrict__ xwb =
        g_xw + (size_t)dir * G4 * M_TOT + (size_t)t0 * B_SZ + b;
    const float* pi = xwb + (size_t)(0 * HALFH + j0 + q) * M_TOT;
    const float* pf = xwb + (size_t)(1 * HALFH + j0 + q) * M_TOT;
    const float* pg = xwb + (size_t)(2 * HALFH + j0 + q) * M_TOT;
    const float* po = xwb + (size_t)(3 * HALFH + j0 + q) * M_TOT;
    const float* pm = mask + (size_t)t0 * B_SZ + b;
    float* pout = out + ((size_t)t0 * B_SZ + b) * 512 + dir * HALFH + j0 + q;
    const ptrdiff_t dout = dstep * 512;

    // Staging: thread covers rows bb = (tid>>6) + {0,4,...,60} at column
    // block kq = (tid & 63)*4; 16 front-batched LDG.128 then 16 STS.128.
    const int st_b0 = tid >> 6;          // 0..3
    const int st_kq = (tid & 63) * 4;    // 0..252
    const float* hsrc0 = &g_h[dir][0][0][0] + (size_t)st_b0 * HALFH + st_kq;
    const size_t hbufoff = (size_t)B_SZ * HALFH;   // floats between buf0/buf1
    // Coalesced write-back base: thread tid<64 writes g_h[buf][tid][j0..j0+3].
    float* hwb0 = &g_h[dir][0][0][0] + (size_t)(tid & 63) * HALFH + j0;

    int rbuf = 0;

    for (int s = 0; s < L_SEQ; s++) {
        // Seed + mask loads issue early; consumed only AFTER the dot loop.
        float ai = __ldcs(pi), af = __ldcs(pf), ag = __ldcs(pg), ao = __ldcs(po);
        float mv = *pm;

        // Stage full h (64x256) from L2 (ldcg: coherent, bypasses stale L1).
        {
            const float* src = hsrc0 + (size_t)rbuf * hbufoff;
            float4 r[16];
#pragma unroll
            for (int i = 0; i < 16; i++)
                r[i] = __ldcg((const float4*)(src + (size_t)(i * 4) * HALFH));
#pragma unroll
            for (int i = 0; i < 16; i++)
                *(float4*)&h_s[st_b0 + i * 4][st_kq] = r[i];
        }
        __syncthreads();

        // K-paired accumulators: acc_r = (sum_{even k}, sum_{odd k}).
        u64 acc0 = 0, acc1 = 0, acc2 = 0, acc3 = 0;

#pragma unroll 8
        for (int k = 0; k < HALFH; k += 4) {
            ulonglong2 hp = *(const ulonglong2*)&h_s[b][k];
            ulonglong2 w0 = *(const ulonglong2*)&Wr0[k];
            ulonglong2 w1 = *(const ulonglong2*)&Wr1[k];
            ulonglong2 w2 = *(const ulonglong2*)&Wr2[k];
            ulonglong2 w3 = *(const ulonglong2*)&Wr3[k];
            acc0 = f2_fma(hp.x, w0.x, acc0);
            acc0 = f2_fma(hp.y, w0.y, acc0);
            acc1 = f2_fma(hp.x, w1.x, acc1);
            acc1 = f2_fma(hp.y, w1.y, acc1);
            acc2 = f2_fma(hp.x, w2.x, acc2);
            acc2 = f2_fma(hp.y, w2.y, acc2);
            acc3 = f2_fma(hp.x, w3.x, acc3);
            acc3 = f2_fma(hp.y, w3.y, acc3);
        }

        // Horizontal add + seeds (seed DRAM latency long hidden by the loop).
        float e0, o0, e1, o1, e2, o2, e3, o3;
        f2_unpack(acc0, e0, o0);
        f2_unpack(acc1, e1, o1);
        f2_unpack(acc2, e2, o2);
        f2_unpack(acc3, e3, o3);
        float gi = e0 + o0 + ai;
        float gf = e1 + o1 + af;
        float gg = e2 + o2 + ag;
        float go = e3 + o3 + ao;
        float si = 1.0f / (1.0f + __expf(-gi));
        float sf = 1.0f / (1.0f + __expf(-gf));
        float so = 1.0f / (1.0f + __expf(-go));
        c = sf * c + si * fast_tanh(gg);
        float h = so * fast_tanh(c);
        h *= mv;
        c *= mv;

        // Coalesced h write-back: gather through smem, 64 STG.128 total.
        hout[q][b] = h;
        __syncthreads();
        if (tid < 64) {
            float4 hv = make_float4(hout[0][tid], hout[1][tid],
                                    hout[2][tid], hout[3][tid]);
            *(float4*)(hwb0 + (size_t)(rbuf ^ 1) * hbufoff) = hv;
        }

        // Barrier arrive (release covers the h STGs via bar.sync HB).
        __syncthreads();
        const unsigned target = base + 2 + s;
        barrier_arrive(dir, blk_local, target, tid);

        // Scattered out store AFTER the release: overlaps the spin.
        *pout = h;

        barrier_spin(dir, target, tid);

        rbuf ^= 1;
        pi += dstep; pf += dstep; pg += dstep; po += dstep;
        pm += dstep; pout += dout;
    }

    // Persist the monotonic base for the next graph replay.
    if (blk_local == 0 && tid == 0)
        st_rel(&g_gen[dir][0], base + 2 + L_SEQ);
}

// ---------------------------------------------------------------------------
// Launch
// d_in: 0=x 1=mask 2=W_ih_f 3=W_hh_f 4=b_ih_f 5=b_hh_f 6=W_ih_b 7=W_hh_b 8=b_ih_b 9=b_hh_b
// ---------------------------------------------------------------------------
extern "C" void kernel_launch(void* const* d_in, const int* in_sizes, int n_in,
                              void* d_out, int out_size)
{
    const float* x     = (const float*)d_in[0];
    const float* mask  = (const float*)d_in[1];
    const float* Wihf  = (const float*)d_in[2];
    const float* Whhf  = (const float*)d_in[3];
    const float* bihf  = (const float*)d_in[4];
    const float* bhhf  = (const float*)d_in[5];
    const float* Wihb  = (const float*)d_in[6];
    const float* Whhb  = (const float*)d_in[7];
    const float* bihb  = (const float*)d_in[8];
    const float* bhhb  = (const float*)d_in[9];
    float* out = (float*)d_out;

    // Idempotent, deterministic; needed for 84 KB dynamic SMEM.
    cudaFuncSetAttribute(lstm_rec_kernel,
                         cudaFuncAttributeMaxDynamicSharedMemorySize, 84224);

    dim3 ggrid(M_TOT / 64, G4 / 64, 2);
    gemm_xw_kernel<<<ggrid, 256>>>(x, Wihf, Wihb, bihf, bhhf, bihb, bhhb);

    lstm_rec_kernel<<<2 * NBPD, 256, 84224>>>(mask, Whhf, Whhb, out);
}